// round 1
// baseline (speedup 1.0000x reference)
#include <cuda_runtime.h>
#include <cstdint>

#define T_TOK 8192
#define HID   1536
#define NEXP  32
#define TOPK  8
#define INTER 512
#define N1    (2*INTER)       // 1024
#define MAXP  (T_TOK*TOPK)    // 65536

// ---- device scratch (allocation-free; __device__ globals per harness rules) ----
__device__ int   g_counts[NEXP];
__device__ int   g_list[NEXP * T_TOK];       // pair-id per expert row
__device__ float g_pairw[MAXP];              // routing weight per (token,slot)
__device__ float g_gu[(size_t)MAXP * N1];    // GEMM1 output (gate|up)
__device__ float g_h [(size_t)MAXP * INTER]; // silu(g)*u
__device__ float g_y [(size_t)MAXP * HID];   // GEMM2 output, scaled

__global__ void reset_kernel() {
    if (threadIdx.x < NEXP) g_counts[threadIdx.x] = 0;
}

// ---------------- Router: one warp per token ----------------
__global__ __launch_bounds__(256) void router_kernel(const float* __restrict__ x,
                                                     const float* __restrict__ gw) {
    const unsigned FULL = 0xffffffffu;
    int warp = (blockIdx.x * blockDim.x + threadIdx.x) >> 5;
    int lane = threadIdx.x & 31;
    if (warp >= T_TOK) return;
    const int t = warp;
    const float4* x4 = (const float4*)(x + (size_t)t * HID);

    float logit = 0.f;
    for (int e = 0; e < NEXP; e++) {
        const float4* g4 = (const float4*)(gw + (size_t)e * HID);
        float s = 0.f;
        for (int k = lane; k < HID / 4; k += 32) {
            float4 a = x4[k], b = g4[k];
            s += a.x * b.x + a.y * b.y + a.z * b.z + a.w * b.w;
        }
        #pragma unroll
        for (int off = 16; off; off >>= 1) s += __shfl_xor_sync(FULL, s, off);
        if (lane == e) logit = s;
    }

    // softmax over 32 experts (lane e owns expert e)
    float m = logit;
    #pragma unroll
    for (int off = 16; off; off >>= 1) m = fmaxf(m, __shfl_xor_sync(FULL, m, off));
    float p = expf(logit - m);
    float sum = p;
    #pragma unroll
    for (int off = 16; off; off >>= 1) sum += __shfl_xor_sync(FULL, sum, off);
    p = p / sum;

    // top-8 (argmax 8x), tie-break to lower index like lax.top_k
    float keep = p;
    float topsum = 0.f;
    int myslot = -1;
    for (int s = 0; s < TOPK; s++) {
        float v = keep; int bl = lane;
        #pragma unroll
        for (int off = 16; off; off >>= 1) {
            float ov = __shfl_down_sync(FULL, v, off);
            int   ol = __shfl_down_sync(FULL, bl, off);
            if (ov > v || (ov == v && ol < bl)) { v = ov; bl = ol; }
        }
        bl = __shfl_sync(FULL, bl, 0);
        v  = __shfl_sync(FULL, v, 0);
        topsum += v;
        if (lane == bl) { myslot = s; keep = -1.f; }
    }

    if (myslot >= 0) {
        int pos = atomicAdd(&g_counts[lane], 1);
        g_list[lane * T_TOK + pos] = t * TOPK + myslot;
        g_pairw[t * TOPK + myslot] = p / topsum;
    }
}

// ---------------- GEMM1: gathered x @ w13_e^T -> g_gu ----------------
// C[m][n] = sum_k A[m][k] * B[n][k];  A row = x[token], B row = w13_e[n]
__global__ __launch_bounds__(256) void gemm1_kernel(const float* __restrict__ x,
                                                    const float* __restrict__ w13) {
    const int e  = blockIdx.z;
    const int M  = g_counts[e];
    const int m0 = blockIdx.y * 128;
    if (m0 >= M) return;
    const int n0 = blockIdx.x * 128;

    __shared__ float As[16][132];
    __shared__ float Bs[16][132];
    __shared__ int   s_pair[128];

    const int tid = threadIdx.x;
    if (tid < 128) {
        int gr = m0 + tid;
        s_pair[tid] = (gr < M) ? g_list[e * T_TOK + gr] : -1;
    }
    __syncthreads();

    // global-load slots: 512 float4 per tile per matrix, 2 per thread
    const int q0 = tid, q1 = tid + 256;
    const int rowA0 = q0 >> 2, kq0 = q0 & 3;
    const int rowA1 = q1 >> 2, kq1 = q1 & 3;
    const int pA0 = s_pair[rowA0], pA1 = s_pair[rowA1];
    const float* aptr0 = (pA0 >= 0) ? x + (size_t)(pA0 >> 3) * HID + kq0 * 4 : nullptr;
    const float* aptr1 = (pA1 >= 0) ? x + (size_t)(pA1 >> 3) * HID + kq1 * 4 : nullptr;
    const float* bbase = w13 + (size_t)e * N1 * HID;
    const float* bptr0 = bbase + (size_t)(n0 + rowA0) * HID + kq0 * 4;
    const float* bptr1 = bbase + (size_t)(n0 + rowA1) * HID + kq1 * 4;

    const int tx = tid & 15, ty = tid >> 4;
    float acc[8][8];
    #pragma unroll
    for (int i = 0; i < 8; i++)
        #pragma unroll
        for (int j = 0; j < 8; j++) acc[i][j] = 0.f;

    for (int k0 = 0; k0 < HID; k0 += 16) {
        float4 a0 = aptr0 ? *(const float4*)(aptr0 + k0) : make_float4(0.f,0.f,0.f,0.f);
        float4 a1 = aptr1 ? *(const float4*)(aptr1 + k0) : make_float4(0.f,0.f,0.f,0.f);
        float4 b0 = *(const float4*)(bptr0 + k0);
        float4 b1 = *(const float4*)(bptr1 + k0);
        __syncthreads();
        As[kq0*4+0][rowA0] = a0.x; As[kq0*4+1][rowA0] = a0.y;
        As[kq0*4+2][rowA0] = a0.z; As[kq0*4+3][rowA0] = a0.w;
        As[kq1*4+0][rowA1] = a1.x; As[kq1*4+1][rowA1] = a1.y;
        As[kq1*4+2][rowA1] = a1.z; As[kq1*4+3][rowA1] = a1.w;
        Bs[kq0*4+0][rowA0] = b0.x; Bs[kq0*4+1][rowA0] = b0.y;
        Bs[kq0*4+2][rowA0] = b0.z; Bs[kq0*4+3][rowA0] = b0.w;
        Bs[kq1*4+0][rowA1] = b1.x; Bs[kq1*4+1][rowA1] = b1.y;
        Bs[kq1*4+2][rowA1] = b1.z; Bs[kq1*4+3][rowA1] = b1.w;
        __syncthreads();
        #pragma unroll
        for (int kk = 0; kk < 16; kk++) {
            float4 av0 = *(const float4*)&As[kk][ty*8];
            float4 av1 = *(const float4*)&As[kk][ty*8+4];
            float4 bv0 = *(const float4*)&Bs[kk][tx*8];
            float4 bv1 = *(const float4*)&Bs[kk][tx*8+4];
            float ar[8] = {av0.x,av0.y,av0.z,av0.w, av1.x,av1.y,av1.z,av1.w};
            float br[8] = {bv0.x,bv0.y,bv0.z,bv0.w, bv1.x,bv1.y,bv1.z,bv1.w};
            #pragma unroll
            for (int i = 0; i < 8; i++)
                #pragma unroll
                for (int j = 0; j < 8; j++) acc[i][j] += ar[i] * br[j];
        }
    }

    #pragma unroll
    for (int i = 0; i < 8; i++) {
        int r = ty*8 + i;
        if (m0 + r < M) {
            int p = s_pair[r];
            float* dst = g_gu + (size_t)p * N1 + n0 + tx*8;
            *(float4*)dst       = make_float4(acc[i][0], acc[i][1], acc[i][2], acc[i][3]);
            *(float4*)(dst + 4) = make_float4(acc[i][4], acc[i][5], acc[i][6], acc[i][7]);
        }
    }
}

// ---------------- SiLU(g) * u ----------------
__global__ void silu_kernel() {
    size_t idx = (size_t)blockIdx.x * blockDim.x + threadIdx.x;
    const size_t total = (size_t)MAXP * (INTER / 4);
    if (idx >= total) return;
    size_t p = idx / (INTER / 4);
    int    j = (int)(idx % (INTER / 4));
    const float4* gu = (const float4*)(g_gu + p * N1);
    float4 g = gu[j];
    float4 u = gu[j + INTER / 4];
    float4 h;
    h.x = g.x / (1.f + expf(-g.x)) * u.x;
    h.y = g.y / (1.f + expf(-g.y)) * u.y;
    h.z = g.z / (1.f + expf(-g.z)) * u.z;
    h.w = g.w / (1.f + expf(-g.w)) * u.w;
    ((float4*)(g_h + p * INTER))[j] = h;
}

// ---------------- GEMM2: gathered h @ w2_e^T -> g_y (scaled by routing weight) ----------------
__global__ __launch_bounds__(256) void gemm2_kernel(const float* __restrict__ w2) {
    const int e  = blockIdx.z;
    const int M  = g_counts[e];
    const int m0 = blockIdx.y * 128;
    if (m0 >= M) return;
    const int n0 = blockIdx.x * 128;

    __shared__ float As[16][132];
    __shared__ float Bs[16][132];
    __shared__ int   s_pair[128];

    const int tid = threadIdx.x;
    if (tid < 128) {
        int gr = m0 + tid;
        s_pair[tid] = (gr < M) ? g_list[e * T_TOK + gr] : -1;
    }
    __syncthreads();

    const int q0 = tid, q1 = tid + 256;
    const int rowA0 = q0 >> 2, kq0 = q0 & 3;
    const int rowA1 = q1 >> 2, kq1 = q1 & 3;
    const int pA0 = s_pair[rowA0], pA1 = s_pair[rowA1];
    const float* aptr0 = (pA0 >= 0) ? g_h + (size_t)pA0 * INTER + kq0 * 4 : nullptr;
    const float* aptr1 = (pA1 >= 0) ? g_h + (size_t)pA1 * INTER + kq1 * 4 : nullptr;
    const float* bbase = w2 + (size_t)e * HID * INTER;
    const float* bptr0 = bbase + (size_t)(n0 + rowA0) * INTER + kq0 * 4;
    const float* bptr1 = bbase + (size_t)(n0 + rowA1) * INTER + kq1 * 4;

    const int tx = tid & 15, ty = tid >> 4;
    float acc[8][8];
    #pragma unroll
    for (int i = 0; i < 8; i++)
        #pragma unroll
        for (int j = 0; j < 8; j++) acc[i][j] = 0.f;

    for (int k0 = 0; k0 < INTER; k0 += 16) {
        float4 a0 = aptr0 ? *(const float4*)(aptr0 + k0) : make_float4(0.f,0.f,0.f,0.f);
        float4 a1 = aptr1 ? *(const float4*)(aptr1 + k0) : make_float4(0.f,0.f,0.f,0.f);
        float4 b0 = *(const float4*)(bptr0 + k0);
        float4 b1 = *(const float4*)(bptr1 + k0);
        __syncthreads();
        As[kq0*4+0][rowA0] = a0.x; As[kq0*4+1][rowA0] = a0.y;
        As[kq0*4+2][rowA0] = a0.z; As[kq0*4+3][rowA0] = a0.w;
        As[kq1*4+0][rowA1] = a1.x; As[kq1*4+1][rowA1] = a1.y;
        As[kq1*4+2][rowA1] = a1.z; As[kq1*4+3][rowA1] = a1.w;
        Bs[kq0*4+0][rowA0] = b0.x; Bs[kq0*4+1][rowA0] = b0.y;
        Bs[kq0*4+2][rowA0] = b0.z; Bs[kq0*4+3][rowA0] = b0.w;
        Bs[kq1*4+0][rowA1] = b1.x; Bs[kq1*4+1][rowA1] = b1.y;
        Bs[kq1*4+2][rowA1] = b1.z; Bs[kq1*4+3][rowA1] = b1.w;
        __syncthreads();
        #pragma unroll
        for (int kk = 0; kk < 16; kk++) {
            float4 av0 = *(const float4*)&As[kk][ty*8];
            float4 av1 = *(const float4*)&As[kk][ty*8+4];
            float4 bv0 = *(const float4*)&Bs[kk][tx*8];
            float4 bv1 = *(const float4*)&Bs[kk][tx*8+4];
            float ar[8] = {av0.x,av0.y,av0.z,av0.w, av1.x,av1.y,av1.z,av1.w};
            float br[8] = {bv0.x,bv0.y,bv0.z,bv0.w, bv1.x,bv1.y,bv1.z,bv1.w};
            #pragma unroll
            for (int i = 0; i < 8; i++)
                #pragma unroll
                for (int j = 0; j < 8; j++) acc[i][j] += ar[i] * br[j];
        }
    }

    #pragma unroll
    for (int i = 0; i < 8; i++) {
        int r = ty*8 + i;
        if (m0 + r < M) {
            int p = s_pair[r];
            float w = g_pairw[p];
            float* dst = g_y + (size_t)p * HID + n0 + tx*8;
            *(float4*)dst       = make_float4(w*acc[i][0], w*acc[i][1], w*acc[i][2], w*acc[i][3]);
            *(float4*)(dst + 4) = make_float4(w*acc[i][4], w*acc[i][5], w*acc[i][6], w*acc[i][7]);
        }
    }
}

// ---------------- deterministic 8-slot reduction -> out ----------------
__global__ void reduce_kernel(float* __restrict__ out) {
    size_t idx = (size_t)blockIdx.x * blockDim.x + threadIdx.x;
    const size_t total = (size_t)T_TOK * (HID / 4);
    if (idx >= total) return;
    size_t t = idx / (HID / 4);
    int    c = (int)(idx % (HID / 4));
    const float4* base = (const float4*)(g_y + t * (size_t)TOPK * HID) + c;
    float4 s = make_float4(0.f, 0.f, 0.f, 0.f);
    #pragma unroll
    for (int sl = 0; sl < TOPK; sl++) {
        float4 v = base[(size_t)sl * (HID / 4)];
        s.x += v.x; s.y += v.y; s.z += v.z; s.w += v.w;
    }
    ((float4*)out)[idx] = s;
}

extern "C" void kernel_launch(void* const* d_in, const int* in_sizes, int n_in,
                              void* d_out, int out_size) {
    (void)in_sizes; (void)n_in; (void)out_size;
    const float* x   = (const float*)d_in[0];
    const float* gw  = (const float*)d_in[1];
    const float* w13 = (const float*)d_in[2];
    const float* w2  = (const float*)d_in[3];
    float* out = (float*)d_out;

    reset_kernel<<<1, 32>>>();
    router_kernel<<<T_TOK / 8, 256>>>(x, gw);
    gemm1_kernel<<<dim3(N1 / 128, T_TOK / 128, NEXP), 256>>>(x, w13);
    silu_kernel<<<(int)(((size_t)MAXP * (INTER / 4)) / 256), 256>>>();
    gemm2_kernel<<<dim3(HID / 128, T_TOK / 128, NEXP), 256>>>(w2);
    reduce_kernel<<<(int)(((size_t)T_TOK * (HID / 4)) / 256), 256>>>(out);
}

// round 3
// speedup vs baseline: 2.6406x; 2.6406x over previous
#include <cuda_runtime.h>
#include <cuda_bf16.h>
#include <cstdint>

#define T_TOK 8192
#define HID   1536
#define NEXP  32
#define TOPK  8
#define INTER 512
#define N1    (2*INTER)       // 1024
#define MAXP  (T_TOK*TOPK)    // 65536

#define STAGE_BYTES 65536     // Ah16K + Al16K + Bh16K + Bl16K
#define SMEM_TOTAL  (1024 + 2*STAGE_BYTES)

// ---------------- device scratch ----------------
__device__ int   g_counts[NEXP];
__device__ int   g_list[NEXP * T_TOK];
__device__ float g_pairw[MAXP];
__device__ __nv_bfloat16 g_xh[(size_t)T_TOK * HID];
__device__ __nv_bfloat16 g_xl[(size_t)T_TOK * HID];
__device__ __nv_bfloat16 g_w13h[(size_t)NEXP * N1 * HID];
__device__ __nv_bfloat16 g_w13l[(size_t)NEXP * N1 * HID];
__device__ __nv_bfloat16 g_w2h[(size_t)NEXP * HID * INTER];
__device__ __nv_bfloat16 g_w2l[(size_t)NEXP * HID * INTER];
__device__ float g_gu[(size_t)MAXP * N1];
__device__ __nv_bfloat16 g_hh[(size_t)MAXP * INTER];
__device__ __nv_bfloat16 g_hl[(size_t)MAXP * INTER];
__device__ float g_y[(size_t)MAXP * HID];

// ---------------- PTX helpers (sm_103-baseline safe: sm_80-era ISA only) ----------------
__device__ __forceinline__ uint32_t smem_u32(const void* p) {
    uint32_t a;
    asm("{ .reg .u64 t; cvta.to.shared.u64 t, %1; cvt.u32.u64 %0, t; }" : "=r"(a) : "l"(p));
    return a;
}
__device__ __forceinline__ uint32_t swz(uint32_t b) { return b ^ ((b >> 3) & 0x70); }

__device__ __forceinline__ void cp16(uint32_t dst, const void* src, bool valid) {
    int sz = valid ? 16 : 0;
    asm volatile("cp.async.cg.shared.global [%0], [%1], 16, %2;\n" :: "r"(dst), "l"(src), "r"(sz));
}
__device__ __forceinline__ void cp_commit() { asm volatile("cp.async.commit_group;" ::: "memory"); }
template <int N> __device__ __forceinline__ void cp_wait() {
    asm volatile("cp.async.wait_group %0;" :: "n"(N) : "memory");
}
__device__ __forceinline__ void ldsm4(uint32_t* r, uint32_t addr) {
    asm volatile("ldmatrix.sync.aligned.m8n8.x4.shared.b16 {%0,%1,%2,%3}, [%4];"
                 : "=r"(r[0]), "=r"(r[1]), "=r"(r[2]), "=r"(r[3]) : "r"(addr));
}
__device__ __forceinline__ void mma16816(float* c, const uint32_t* a, const uint32_t* b) {
    asm volatile("mma.sync.aligned.m16n8k16.row.col.f32.bf16.bf16.f32 "
                 "{%0,%1,%2,%3}, {%4,%5,%6,%7}, {%8,%9}, {%0,%1,%2,%3};"
                 : "+f"(c[0]), "+f"(c[1]), "+f"(c[2]), "+f"(c[3])
                 : "r"(a[0]), "r"(a[1]), "r"(a[2]), "r"(a[3]), "r"(b[0]), "r"(b[1]));
}
__device__ __forceinline__ unsigned short bfbits(float f) {
    __nv_bfloat16 b = __float2bfloat16(f);
    return *reinterpret_cast<unsigned short*>(&b);
}

// ---------------- reset ----------------
__global__ void reset_kernel() {
    if (threadIdx.x < NEXP) g_counts[threadIdx.x] = 0;
}

// ---------------- fp32 -> bf16 hi/lo split ----------------
__device__ __forceinline__ void cvt_body(const float4* __restrict__ src, uint2* __restrict__ hi,
                                         uint2* __restrict__ lo, int n4) {
    int i = blockIdx.x * blockDim.x + threadIdx.x;
    if (i >= n4) return;
    float4 v = src[i];
    __nv_bfloat16 h0 = __float2bfloat16(v.x), h1 = __float2bfloat16(v.y);
    __nv_bfloat16 h2 = __float2bfloat16(v.z), h3 = __float2bfloat16(v.w);
    float r0 = v.x - __bfloat162float(h0), r1 = v.y - __bfloat162float(h1);
    float r2 = v.z - __bfloat162float(h2), r3 = v.w - __bfloat162float(h3);
    uint2 hv, lv;
    hv.x = (uint32_t)*reinterpret_cast<unsigned short*>(&h0) | ((uint32_t)*reinterpret_cast<unsigned short*>(&h1) << 16);
    hv.y = (uint32_t)*reinterpret_cast<unsigned short*>(&h2) | ((uint32_t)*reinterpret_cast<unsigned short*>(&h3) << 16);
    lv.x = (uint32_t)bfbits(r0) | ((uint32_t)bfbits(r1) << 16);
    lv.y = (uint32_t)bfbits(r2) | ((uint32_t)bfbits(r3) << 16);
    hi[i] = hv;
    lo[i] = lv;
}
__global__ void cvt_x_kernel(const float* __restrict__ x) {
    cvt_body((const float4*)x, (uint2*)g_xh, (uint2*)g_xl, T_TOK * HID / 4);
}
__global__ void cvt_w13_kernel(const float* __restrict__ w) {
    cvt_body((const float4*)w, (uint2*)g_w13h, (uint2*)g_w13l, NEXP * N1 * HID / 4);
}
__global__ void cvt_w2_kernel(const float* __restrict__ w) {
    cvt_body((const float4*)w, (uint2*)g_w2h, (uint2*)g_w2l, NEXP * HID * INTER / 4);
}

// ---------------- Router: one warp per token (fp32, exact) ----------------
__global__ __launch_bounds__(256) void router_kernel(const float* __restrict__ x,
                                                     const float* __restrict__ gw) {
    const unsigned FULL = 0xffffffffu;
    int warp = (blockIdx.x * blockDim.x + threadIdx.x) >> 5;
    int lane = threadIdx.x & 31;
    if (warp >= T_TOK) return;
    const int t = warp;
    const float4* x4 = (const float4*)(x + (size_t)t * HID);

    float logit = 0.f;
    for (int e = 0; e < NEXP; e++) {
        const float4* g4 = (const float4*)(gw + (size_t)e * HID);
        float s = 0.f;
        for (int k = lane; k < HID / 4; k += 32) {
            float4 a = x4[k], b = g4[k];
            s += a.x * b.x + a.y * b.y + a.z * b.z + a.w * b.w;
        }
        #pragma unroll
        for (int off = 16; off; off >>= 1) s += __shfl_xor_sync(FULL, s, off);
        if (lane == e) logit = s;
    }
    float m = logit;
    #pragma unroll
    for (int off = 16; off; off >>= 1) m = fmaxf(m, __shfl_xor_sync(FULL, m, off));
    float p = expf(logit - m);
    float sum = p;
    #pragma unroll
    for (int off = 16; off; off >>= 1) sum += __shfl_xor_sync(FULL, sum, off);
    p = p / sum;

    float keep = p, topsum = 0.f;
    int myslot = -1;
    for (int s = 0; s < TOPK; s++) {
        float v = keep; int bl = lane;
        #pragma unroll
        for (int off = 16; off; off >>= 1) {
            float ov = __shfl_down_sync(FULL, v, off);
            int   ol = __shfl_down_sync(FULL, bl, off);
            if (ov > v || (ov == v && ol < bl)) { v = ov; bl = ol; }
        }
        bl = __shfl_sync(FULL, bl, 0);
        v  = __shfl_sync(FULL, v, 0);
        topsum += v;
        if (lane == bl) { myslot = s; keep = -1.f; }
    }
    if (myslot >= 0) {
        int pos = atomicAdd(&g_counts[lane], 1);
        g_list[lane * T_TOK + pos] = t * TOPK + myslot;
        g_pairw[t * TOPK + myslot] = p / topsum;
    }
}

// ================= HMMA GEMM core (split bf16, 3-pass, fp32 reg accum) =================
// CTA tile 128(M) x 128(N), K-slab 64. 8 warps (2x4). Warp tile 64x32.
// smem stage: Ah[128][64] Al Bh[128][64] Bl, 128B rows, XOR-128 swizzled.

struct FragState {
    uint32_t a_row, a_kb, b_row, b_kb;  // per-thread ldmatrix coords
};

__device__ __forceinline__ FragState frag_init(int wid, int lane) {
    FragState f;
    int warp_m = wid >> 2, warp_n = wid & 3;
    f.a_row = warp_m * 64 + (lane & 15);
    f.a_kb  = (lane >> 4) * 16;
    f.b_row = warp_n * 32 + (lane & 7) + ((lane >> 4) << 3);
    f.b_kb  = ((lane >> 3) & 1) * 16;
    return f;
}

// compute one k-slab (64) from stage base; acc[4][4][4]
__device__ __forceinline__ void slab_mma(uint32_t st, const FragState& f, float acc[4][4][4]) {
    const uint32_t sAh = st, sAl = st + 16384, sBh = st + 32768, sBl = st + 49152;
    #pragma unroll
    for (int ks = 0; ks < 4; ks++) {
        uint32_t ah[4][4], al[4][4], bh[4][2], bl[4][2];
        #pragma unroll
        for (int m = 0; m < 4; m++) {
            uint32_t off = (f.a_row + m * 16) * 128 + ks * 32 + f.a_kb;
            ldsm4(ah[m], sAh + swz(off));
            ldsm4(al[m], sAl + swz(off));
        }
        #pragma unroll
        for (int j = 0; j < 2; j++) {
            uint32_t off = (f.b_row + j * 16) * 128 + ks * 32 + f.b_kb;
            uint32_t t[4];
            ldsm4(t, sBh + swz(off));
            bh[2*j][0] = t[0]; bh[2*j][1] = t[1]; bh[2*j+1][0] = t[2]; bh[2*j+1][1] = t[3];
            ldsm4(t, sBl + swz(off));
            bl[2*j][0] = t[0]; bl[2*j][1] = t[1]; bl[2*j+1][0] = t[2]; bl[2*j+1][1] = t[3];
        }
        #pragma unroll
        for (int m = 0; m < 4; m++)
            #pragma unroll
            for (int n = 0; n < 4; n++) {
                mma16816(acc[m][n], ah[m], bh[n]);
                mma16816(acc[m][n], ah[m], bl[n]);
                mma16816(acc[m][n], al[m], bh[n]);
            }
    }
}

// ---------------- GEMM1: gathered x @ w13^T -> g_gu (fp32) ----------------
__global__ __launch_bounds__(256, 1) void gemm1_mma() {
    const int e  = blockIdx.z;
    const int M  = g_counts[e];
    const int m0 = blockIdx.y * 128;
    if (m0 >= M) return;
    const int n0 = blockIdx.x * 128;

    extern __shared__ char dsm[];
    int* s_pair = (int*)dsm;
    const uint32_t TILE = smem_u32(dsm) + 1024;

    const int tid = threadIdx.x, wid = tid >> 5, lane = tid & 31;
    if (tid < 128) {
        int gr = m0 + tid;
        s_pair[tid] = (gr < M) ? g_list[e * T_TOK + gr] : -1;
    }
    __syncthreads();

    // copy slots: 1024 16B chunks per matrix, 4 per thread
    size_t offA[4]; uint32_t dst[4]; bool vA[4];
    size_t offB[4];
    #pragma unroll
    for (int i = 0; i < 4; i++) {
        int c = tid + i * 256, r = c >> 3, cw = c & 7;
        int p = s_pair[r];
        vA[i] = (p >= 0);
        offA[i] = (size_t)(vA[i] ? (p >> 3) : 0) * HID + cw * 8;
        offB[i] = ((size_t)e * N1 + n0 + r) * HID + cw * 8;
        dst[i] = swz(r * 128 + cw * 16);
    }

    auto load_stage = [&](int b, int k0) {
        uint32_t st = TILE + b * STAGE_BYTES;
        #pragma unroll
        for (int i = 0; i < 4; i++) {
            cp16(st + dst[i],         g_xh   + offA[i] + k0, vA[i]);
            cp16(st + 16384 + dst[i], g_xl   + offA[i] + k0, vA[i]);
            cp16(st + 32768 + dst[i], g_w13h + offB[i] + k0, true);
            cp16(st + 49152 + dst[i], g_w13l + offB[i] + k0, true);
        }
        cp_commit();
    };

    FragState f = frag_init(wid, lane);
    float acc[4][4][4];
    #pragma unroll
    for (int m = 0; m < 4; m++)
        #pragma unroll
        for (int n = 0; n < 4; n++)
            #pragma unroll
            for (int k = 0; k < 4; k++) acc[m][n][k] = 0.f;

    const int S = HID / 64;  // 24
    load_stage(0, 0);
    load_stage(1, 64);
    for (int s = 0; s < S; s++) {
        const int b = s & 1;
        if (s + 1 < S) cp_wait<1>(); else cp_wait<0>();
        __syncthreads();
        slab_mma(TILE + b * STAGE_BYTES, f, acc);
        __syncthreads();
        if (s + 2 < S) load_stage(b, (s + 2) * 64);
    }

    // epilogue: write fp32 gu
    const int g = lane >> 2, tg = lane & 3;
    const int warp_m = wid >> 2, warp_n = wid & 3;
    #pragma unroll
    for (int m = 0; m < 4; m++) {
        int lr = warp_m * 64 + m * 16 + g;
        int p0 = s_pair[lr], p1 = s_pair[lr + 8];
        #pragma unroll
        for (int n = 0; n < 4; n++) {
            int col = n0 + warp_n * 32 + n * 8 + tg * 2;
            if (p0 >= 0) *(float2*)(g_gu + (size_t)p0 * N1 + col) = make_float2(acc[m][n][0], acc[m][n][1]);
            if (p1 >= 0) *(float2*)(g_gu + (size_t)p1 * N1 + col) = make_float2(acc[m][n][2], acc[m][n][3]);
        }
    }
}

// ---------------- SiLU(g)*u -> bf16 hi/lo ----------------
__global__ void silu_kernel() {
    size_t idx = (size_t)blockIdx.x * blockDim.x + threadIdx.x;
    const size_t total = (size_t)MAXP * (INTER / 4);
    if (idx >= total) return;
    size_t p = idx / (INTER / 4);
    int    j = (int)(idx % (INTER / 4));
    const float4* gu = (const float4*)(g_gu + p * N1);
    float4 gg = gu[j];
    float4 uu = gu[j + INTER / 4];
    float h0 = gg.x / (1.f + expf(-gg.x)) * uu.x;
    float h1 = gg.y / (1.f + expf(-gg.y)) * uu.y;
    float h2 = gg.z / (1.f + expf(-gg.z)) * uu.z;
    float h3 = gg.w / (1.f + expf(-gg.w)) * uu.w;
    __nv_bfloat16 b0 = __float2bfloat16(h0), b1 = __float2bfloat16(h1);
    __nv_bfloat16 b2 = __float2bfloat16(h2), b3 = __float2bfloat16(h3);
    uint2 hv, lv;
    hv.x = (uint32_t)*reinterpret_cast<unsigned short*>(&b0) | ((uint32_t)*reinterpret_cast<unsigned short*>(&b1) << 16);
    hv.y = (uint32_t)*reinterpret_cast<unsigned short*>(&b2) | ((uint32_t)*reinterpret_cast<unsigned short*>(&b3) << 16);
    lv.x = (uint32_t)bfbits(h0 - __bfloat162float(b0)) | ((uint32_t)bfbits(h1 - __bfloat162float(b1)) << 16);
    lv.y = (uint32_t)bfbits(h2 - __bfloat162float(b2)) | ((uint32_t)bfbits(h3 - __bfloat162float(b3)) << 16);
    ((uint2*)(g_hh + p * INTER))[j] = hv;
    ((uint2*)(g_hl + p * INTER))[j] = lv;
}

// ---------------- GEMM2: gathered h @ w2^T -> g_y (scaled) ----------------
__global__ __launch_bounds__(256, 1) void gemm2_mma() {
    const int e  = blockIdx.z;
    const int M  = g_counts[e];
    const int m0 = blockIdx.y * 128;
    if (m0 >= M) return;
    const int n0 = blockIdx.x * 128;

    extern __shared__ char dsm[];
    int* s_pair = (int*)dsm;
    const uint32_t TILE = smem_u32(dsm) + 1024;

    const int tid = threadIdx.x, wid = tid >> 5, lane = tid & 31;
    if (tid < 128) {
        int gr = m0 + tid;
        s_pair[tid] = (gr < M) ? g_list[e * T_TOK + gr] : -1;
    }
    __syncthreads();

    size_t offA[4]; uint32_t dst[4]; bool vA[4];
    size_t offB[4];
    #pragma unroll
    for (int i = 0; i < 4; i++) {
        int c = tid + i * 256, r = c >> 3, cw = c & 7;
        int p = s_pair[r];
        vA[i] = (p >= 0);
        offA[i] = (size_t)(vA[i] ? p : 0) * INTER + cw * 8;
        offB[i] = ((size_t)e * HID + n0 + r) * INTER + cw * 8;
        dst[i] = swz(r * 128 + cw * 16);
    }

    auto load_stage = [&](int b, int k0) {
        uint32_t st = TILE + b * STAGE_BYTES;
        #pragma unroll
        for (int i = 0; i < 4; i++) {
            cp16(st + dst[i],         g_hh  + offA[i] + k0, vA[i]);
            cp16(st + 16384 + dst[i], g_hl  + offA[i] + k0, vA[i]);
            cp16(st + 32768 + dst[i], g_w2h + offB[i] + k0, true);
            cp16(st + 49152 + dst[i], g_w2l + offB[i] + k0, true);
        }
        cp_commit();
    };

    FragState f = frag_init(wid, lane);
    float acc[4][4][4];
    #pragma unroll
    for (int m = 0; m < 4; m++)
        #pragma unroll
        for (int n = 0; n < 4; n++)
            #pragma unroll
            for (int k = 0; k < 4; k++) acc[m][n][k] = 0.f;

    const int S = INTER / 64;  // 8
    load_stage(0, 0);
    load_stage(1, 64);
    for (int s = 0; s < S; s++) {
        const int b = s & 1;
        if (s + 1 < S) cp_wait<1>(); else cp_wait<0>();
        __syncthreads();
        slab_mma(TILE + b * STAGE_BYTES, f, acc);
        __syncthreads();
        if (s + 2 < S) load_stage(b, (s + 2) * 64);
    }

    const int g = lane >> 2, tg = lane & 3;
    const int warp_m = wid >> 2, warp_n = wid & 3;
    #pragma unroll
    for (int m = 0; m < 4; m++) {
        int lr = warp_m * 64 + m * 16 + g;
        int p0 = s_pair[lr], p1 = s_pair[lr + 8];
        float w0 = (p0 >= 0) ? g_pairw[p0] : 0.f;
        float w1 = (p1 >= 0) ? g_pairw[p1] : 0.f;
        #pragma unroll
        for (int n = 0; n < 4; n++) {
            int col = n0 + warp_n * 32 + n * 8 + tg * 2;
            if (p0 >= 0) *(float2*)(g_y + (size_t)p0 * HID + col) = make_float2(w0 * acc[m][n][0], w0 * acc[m][n][1]);
            if (p1 >= 0) *(float2*)(g_y + (size_t)p1 * HID + col) = make_float2(w1 * acc[m][n][2], w1 * acc[m][n][3]);
        }
    }
}

// ---------------- deterministic 8-slot reduction ----------------
__global__ void reduce_kernel(float* __restrict__ out) {
    size_t idx = (size_t)blockIdx.x * blockDim.x + threadIdx.x;
    const size_t total = (size_t)T_TOK * (HID / 4);
    if (idx >= total) return;
    size_t t = idx / (HID / 4);
    int    c = (int)(idx % (HID / 4));
    const float4* base = (const float4*)(g_y + t * (size_t)TOPK * HID) + c;
    float4 s = make_float4(0.f, 0.f, 0.f, 0.f);
    #pragma unroll
    for (int sl = 0; sl < TOPK; sl++) {
        float4 v = base[(size_t)sl * (HID / 4)];
        s.x += v.x; s.y += v.y; s.z += v.z; s.w += v.w;
    }
    ((float4*)out)[idx] = s;
}

extern "C" void kernel_launch(void* const* d_in, const int* in_sizes, int n_in,
                              void* d_out, int out_size) {
    (void)in_sizes; (void)n_in; (void)out_size;
    const float* x   = (const float*)d_in[0];
    const float* gw  = (const float*)d_in[1];
    const float* w13 = (const float*)d_in[2];
    const float* w2  = (const float*)d_in[3];
    float* out = (float*)d_out;

    cudaFuncSetAttribute(gemm1_mma, cudaFuncAttributeMaxDynamicSharedMemorySize, SMEM_TOTAL);
    cudaFuncSetAttribute(gemm2_mma, cudaFuncAttributeMaxDynamicSharedMemorySize, SMEM_TOTAL);

    reset_kernel<<<1, 32>>>();
    cvt_x_kernel<<<(T_TOK * HID / 4 + 255) / 256, 256>>>(x);
    cvt_w13_kernel<<<(NEXP * N1 * HID / 4 + 255) / 256, 256>>>(w13);
    cvt_w2_kernel<<<(NEXP * HID * INTER / 4 + 255) / 256, 256>>>(w2);
    router_kernel<<<T_TOK / 8, 256>>>(x, gw);
    gemm1_mma<<<dim3(N1 / 128, 64, NEXP), 256, SMEM_TOTAL>>>();
    silu_kernel<<<(int)(((size_t)MAXP * (INTER / 4)) / 256), 256>>>();
    gemm2_mma<<<dim3(HID / 128, 64, NEXP), 256, SMEM_TOTAL>>>();
    reduce_kernel<<<(int)(((size_t)T_TOK * (HID / 4)) / 256), 256>>>(out);
}